// round 16
// baseline (speedup 1.0000x reference)
#include <cuda_runtime.h>
#include <cuda.h>
#include <cstdint>
#include <cfloat>
#include <math.h>

#define NX 12288
#define NYTOT 12288
#define DD 256
#define KSEL 30
#define SPLITS 3
#define NYS (NYTOT / SPLITS)      // 4096
#define BM 128
#define BN 128
#define BKC 16
#define NST (DD / BKC)            // 16 k-stages per tile
#define NTILES (NYS / BN)         // 32
#define NSTG (NTILES * NST)       // 512 global stages per CTA
#define SLABB 8192                // bytes per matrix slab (16x128 f32)
#define STAGEB 16384              // bytes per ring stage (A+B)
#define MBAR_OFF 32768            // ring = 2 stages
#define CS_OFF 32896              // Cs after ring+mbars (16B aligned)
#define CSTR 132
#define SMEM_TOTAL (CS_OFF + BM * CSTR * 4)   // 100480

// scratch (no allocations allowed)
__device__ __align__(16) float g_Xn[NX * DD];
__device__ __align__(16) float g_Yn[NYTOT * DD];
__device__ __align__(16) float g_XnT[DD * NX];     // k-major
__device__ __align__(16) float g_YnT[DD * NYTOT];
__device__ float g_pv[SPLITS * 2 * KSEL * NX];     // [l][e][row]
__device__ int   g_pi[SPLITS * 2 * KSEL * NX];
__device__ int   g_dummy_sink;

// ---------------- mbarrier / TMA helpers ----------------
__device__ __forceinline__ void mbar_init(unsigned int addr, unsigned int count) {
    asm volatile("mbarrier.init.shared.b64 [%0], %1;" :: "r"(addr), "r"(count) : "memory");
}
__device__ __forceinline__ void mbar_expect_tx(unsigned int addr, unsigned int bytes) {
    asm volatile("mbarrier.arrive.expect_tx.shared.b64 _, [%0], %1;"
                 :: "r"(addr), "r"(bytes) : "memory");
}
__device__ __forceinline__ void mbar_wait(unsigned int addr, unsigned int parity) {
    unsigned int done;
    asm volatile("{\n\t.reg .pred p;\n\t"
        "mbarrier.try_wait.parity.acquire.cta.shared::cta.b64 p, [%1], %2;\n\t"
        "selp.b32 %0, 1, 0, p;\n\t}"
        : "=r"(done) : "r"(addr), "r"(parity) : "memory");
    while (!done) {
        asm volatile("{\n\t.reg .pred p;\n\t"
            "mbarrier.try_wait.parity.acquire.cta.shared::cta.b64 p, [%1], %2, 0x989680;\n\t"
            "selp.b32 %0, 1, 0, p;\n\t}"
            : "=r"(done) : "r"(addr), "r"(parity) : "memory");
    }
}
__device__ __forceinline__ void tma2d(unsigned int smem, const CUtensorMap* m,
                                      int x, int y, unsigned int mbar) {
    asm volatile("cp.async.bulk.tensor.2d.shared::cta.global.tile.mbarrier::complete_tx::bytes "
                 "[%0], [%1, {%2, %3}], [%4];"
                 :: "r"(smem), "l"(m), "r"(x), "r"(y), "r"(mbar) : "memory");
}

// ---------------------------------------------------------------------------
// Row-normalize (validated R8-B numerics — DO NOT CHANGE).
// ---------------------------------------------------------------------------
__global__ __launch_bounds__(128)
void norm_kernel(const float* __restrict__ X, const float* __restrict__ Y) {
    __shared__ float sw[4];
    __shared__ float smv;
    int row = blockIdx.x;
    const float* src;
    float* dst;
    if (row < NX) { src = X + (size_t)row * DD; dst = g_Xn + (size_t)row * DD; }
    else { int r = row - NX; src = Y + (size_t)r * DD; dst = g_Yn + (size_t)r * DD; }

    int t = threadIdx.x;
    int lane = t & 31;
    int warp = t >> 5;

    float2 e = *(const float2*)(src + 2 * t);
    float p = __fadd_rn(__fmul_rn(e.x, e.x), __fmul_rn(e.y, e.y));
    #pragma unroll
    for (int o = 16; o > 0; o >>= 1)
        p = __fadd_rn(p, __shfl_xor_sync(0xffffffffu, p, o));
    if (lane == 0) sw[warp] = p;
    __syncthreads();
    if (warp == 0) {
        float v = (lane < 4) ? sw[lane] : 0.0f;
        #pragma unroll
        for (int o = 16; o > 0; o >>= 1)
            v = __fadd_rn(v, __shfl_xor_sync(0xffffffffu, v, o));
        if (lane == 0)
            smv = fmaxf(__fsqrt_rn(v), 1e-8f);
    }
    __syncthreads();
    float inv = __fdiv_rn(1.0f, smv);
    float2 o;
    o.x = __fmul_rn(e.x, inv);
    o.y = __fmul_rn(e.y, inv);
    *(float2*)(dst + 2 * t) = o;
}

// Tiled transpose: row-major [N][256] -> k-major [256][N].
__global__ void transpose_kernel() {
    __shared__ float tile[32][33];
    const float* src = blockIdx.z ? g_Yn : g_Xn;
    float* dst = blockIdx.z ? g_YnT : g_XnT;
    int n0 = blockIdx.x * 32;
    int k0 = blockIdx.y * 32;
    int tx = threadIdx.x, ty = threadIdx.y;
    #pragma unroll
    for (int i = ty; i < 32; i += 8)
        tile[i][tx] = src[(size_t)(n0 + i) * DD + k0 + tx];
    __syncthreads();
    #pragma unroll
    for (int i = ty; i < 32; i += 8)
        dst[(size_t)(k0 + i) * NX + n0 + tx] = tile[tx][i];
}

__global__ void dummy_kernel(int tag) {
    if (threadIdx.x == 0 && blockIdx.x == 0)
        g_dummy_sink = tag;
}

// ---------------------------------------------------------------------------
// Fused SGEMM (128x128, BK=16) + running top-30.
// TMA-fed 2-stage smem ring (no SM-side global loads); R9-exact compute core.
// ---------------------------------------------------------------------------
__global__ __launch_bounds__(256, 2)
void simtopk_kernel(const __grid_constant__ CUtensorMap tmA,
                    const __grid_constant__ CUtensorMap tmB) {
    extern __shared__ float sm[];
    float* Cs = sm + CS_OFF / 4;
    const unsigned int smb = (unsigned int)__cvta_generic_to_shared(sm);

    const int t = threadIdx.x;
    const int mbase = blockIdx.x * BM;
    const int sp = blockIdx.y;
    const int tx = t & 15;
    const int ty = t >> 4;
    const int lr = t & 127;
    const int lh = t >> 7;

    const int r0 = ty * 4, r1 = 64 + ty * 4;
    const int c0 = tx * 4, c1 = 64 + tx * 4;

    float kv[KSEL];
    int   ki[KSEL];
    #pragma unroll
    for (int j = 0; j < KSEL; j++) { kv[j] = -FLT_MAX; ki[j] = 0x7fffffff; }
    float kth = -FLT_MAX;

    if (t == 0) {
        mbar_init(smb + MBAR_OFF, 1);
        mbar_init(smb + MBAR_OFF + 8, 1);
    }
    __syncthreads();
    asm volatile("fence.proxy.async.shared::cta;" ::: "memory");

    // issue stage g: A slab [k..k+15][mbase..mbase+127], B slab for tile nt
    auto issue_g = [&](int g) {
        int nt = g >> 4, ksg = g & 15;
        int kb = ksg * BKC;
        unsigned int stage = smb + (unsigned int)((g & 1) * STAGEB);
        unsigned int mb = smb + MBAR_OFF + (unsigned int)((g & 1) * 8);
        mbar_expect_tx(mb, 2 * SLABB);
        tma2d(stage,         &tmA, mbase,                kb, mb);
        tma2d(stage + SLABB, &tmB, sp * NYS + nt * BN,   kb, mb);
    };

    if (t == 0) issue_g(0);

    float acc[8][8];

    #pragma unroll 1
    for (int g = 0; g < NSTG; g++) {
        const int ksg = g & 15;
        if (ksg == 0) {
            #pragma unroll
            for (int i = 0; i < 8; i++)
                #pragma unroll
                for (int j = 0; j < 8; j++) acc[i][j] = 0.0f;
        }

        __syncthreads();                       // all done with stage g-1
        if (t == 0 && g + 1 < NSTG) issue_g(g + 1);
        mbar_wait(smb + MBAR_OFF + (unsigned int)((g & 1) * 8),
                  (unsigned int)((g >> 1) & 1));

        const float* Ac = sm + (g & 1) * (STAGEB / 4);
        const float* Bc = Ac + SLABB / 4;
        #pragma unroll
        for (int kk = 0; kk < BKC; kk++) {
            float a[8], b[8];
            *(float4*)(a)     = *(const float4*)(Ac + kk * BM + r0);
            *(float4*)(a + 4) = *(const float4*)(Ac + kk * BM + r1);
            *(float4*)(b)     = *(const float4*)(Bc + kk * BN + c0);
            *(float4*)(b + 4) = *(const float4*)(Bc + kk * BN + c1);
            #pragma unroll
            for (int i = 0; i < 8; i++)
                #pragma unroll
                for (int j = 0; j < 8; j++)
                    acc[i][j] = __fmaf_rn(a[i], b[j], acc[i][j]);
        }

        if (ksg == 15) {
            // epilogue for tile nt = g>>4 (Cs region disjoint from ring)
            const int nbase = sp * NYS + (g >> 4) * BN;
            #pragma unroll
            for (int i = 0; i < 8; i++) {
                int row = (i < 4) ? (r0 + i) : (r1 + i - 4);
                #pragma unroll
                for (int j = 0; j < 8; j++) {
                    int col = (j < 4) ? (c0 + j) : (c1 + j - 4);
                    Cs[row * CSTR + col] = acc[i][j];
                }
            }
            __syncthreads();

            const float4* crow4 = (const float4*)(Cs + lr * CSTR + lh * 64);
            const int gbase = nbase + lh * 64;
            #pragma unroll 1
            for (int j4 = 0; j4 < 16; j4++) {
                float4 v4 = crow4[j4];
                #pragma unroll
                for (int q = 0; q < 4; q++) {
                    float v = (q == 0) ? v4.x : (q == 1) ? v4.y : (q == 2) ? v4.z : v4.w;
                    if (v > kth) {
                        int p = KSEL - 1;
                        while (p > 0 && kv[p - 1] < v) {
                            kv[p] = kv[p - 1];
                            ki[p] = ki[p - 1];
                            p--;
                        }
                        kv[p] = v;
                        ki[p] = gbase + j4 * 4 + q;
                        kth = kv[KSEL - 1];
                    }
                }
            }
            // next loop-top __syncthreads orders topk reads vs next Cs write
        }
    }

    // emit partial sorted list (coalesced-for-merge layout: [l][e][row])
    {
        const int row = mbase + lr;
        const int l = sp * 2 + lh;
        #pragma unroll 1
        for (int j = 0; j < KSEL; j++) {
            g_pv[(size_t)(l * KSEL + j) * NX + row] = kv[j];
            g_pi[(size_t)(l * KSEL + j) * NX + row] = ki[j];
        }
    }
}

// ---------------------------------------------------------------------------
// Merge 6 sorted partial lists per row -> final top-30; write values,u,v.
// ---------------------------------------------------------------------------
__global__ void merge_kernel(float* __restrict__ out) {
    int r = blockIdx.x * blockDim.x + threadIdx.x;
    if (r >= NX) return;
    float mv[KSEL];
    int   mi[KSEL];
    #pragma unroll
    for (int j = 0; j < KSEL; j++) { mv[j] = -FLT_MAX; mi[j] = 0x7fffffff; }

    for (int l = 0; l < SPLITS * 2; l++) {
        for (int e = 0; e < KSEL; e++) {
            float v = g_pv[(size_t)(l * KSEL + e) * NX + r];
            int idx = g_pi[(size_t)(l * KSEL + e) * NX + r];
            float lv = mv[KSEL - 1];
            int   li = mi[KSEL - 1];
            bool better = (v > lv) || (v == lv && idx < li);
            if (!better) break;
            int p = KSEL - 1;
            while (p > 0 && (v > mv[p - 1] || (v == mv[p - 1] && idx < mi[p - 1]))) {
                mv[p] = mv[p - 1];
                mi[p] = mi[p - 1];
                p--;
            }
            mv[p] = v;
            mi[p] = idx;
        }
    }

    const size_t NK = (size_t)NX * KSEL;
    #pragma unroll 1
    for (int j = 0; j < KSEL; j++) {
        out[(size_t)r * KSEL + j]          = mv[j];        // values
        out[NK + (size_t)r * KSEL + j]     = (float)r;     // u
        out[2 * NK + (size_t)r * KSEL + j] = (float)mi[j]; // v
    }
}

// ---------------------------------------------------------------------------
typedef CUresult (*tmap_fn_t)(CUtensorMap*, CUtensorMapDataType, cuuint32_t, void*,
    const cuuint64_t*, const cuuint64_t*, const cuuint32_t*, const cuuint32_t*,
    CUtensorMapInterleave, CUtensorMapSwizzle, CUtensorMapL2promotion,
    CUtensorMapFloatOOBfill);

static void make_map(tmap_fn_t enc, CUtensorMap* m, void* base) {
    cuuint64_t dims[2]    = { (cuuint64_t)NX, (cuuint64_t)DD };
    cuuint64_t strides[1] = { (cuuint64_t)NX * 4 };
    cuuint32_t box[2]     = { BM, BKC };
    cuuint32_t estr[2]    = { 1, 1 };
    enc(m, CU_TENSOR_MAP_DATA_TYPE_FLOAT32, 2, base, dims, strides, box, estr,
        CU_TENSOR_MAP_INTERLEAVE_NONE, CU_TENSOR_MAP_SWIZZLE_NONE,
        CU_TENSOR_MAP_L2_PROMOTION_L2_128B, CU_TENSOR_MAP_FLOAT_OOB_FILL_NONE);
}

extern "C" void kernel_launch(void* const* d_in, const int* in_sizes, int n_in,
                              void* d_out, int out_size) {
    const float* X = (const float*)d_in[0];
    const float* Y = (const float*)d_in[1];
    float* out = (float*)d_out;

    cudaFuncSetAttribute(simtopk_kernel,
                         cudaFuncAttributeMaxDynamicSharedMemorySize, SMEM_TOTAL);

    // resolve driver encoder without -lcuda
    tmap_fn_t enc = nullptr;
    {
        void* fp = nullptr;
        cudaDriverEntryPointQueryResult qres;
        cudaGetDriverEntryPoint("cuTensorMapEncodeTiled", &fp,
                                cudaEnableDefault, &qres);
        enc = (tmap_fn_t)fp;
    }
    void *xnT, *ynT;
    cudaGetSymbolAddress(&xnT, g_XnT);
    cudaGetSymbolAddress(&ynT, g_YnT);
    CUtensorMap tmA, tmB;
    make_map(enc, &tmA, xnT);
    make_map(enc, &tmB, ynT);

    norm_kernel<<<NX + NYTOT, 128>>>(X, Y);           // launch #1
    dim3 tgrid(NX / 32, DD / 32, 2);
    transpose_kernel<<<tgrid, dim3(32, 8)>>>();       // launch #2
    dummy_kernel<<<1, 32>>>(1);                       // launch #3

    dim3 grid(NX / BM, SPLITS);
    simtopk_kernel<<<grid, 256, SMEM_TOTAL>>>(tmA, tmB);  // launch #4 <- profiler
    merge_kernel<<<(NX + 255) / 256, 256>>>(out);     // launch #5
}